// round 2
// baseline (speedup 1.0000x reference)
#include <cuda_runtime.h>
#include <cuda_fp16.h>
#include <math.h>

#define FULLM 0xffffffffu
static const int NMAX = 100352;
static const int EMAX = 1700000;

// ---------------- device scratch (static: no allocation allowed) ----------------
__device__ int      d_is64;
__device__ int      d_cnt[NMAX];
__device__ int      d_cur[NMAX];
__device__ int      d_off[NMAX + 1];
__device__ float    d_dinv[NMAX];
__device__ int      d_col[EMAX];
__device__ unsigned d_bits0[NMAX * 8];
__device__ unsigned d_bits1[NMAX * 4];
__device__ unsigned d_bits2[NMAX * 4];
__device__ __align__(16) __half2 d_g[NMAX * 64];   // cnt values, exact integers in fp16
__device__ float    d_mu[256];
__device__ float    d_part[512 * 256];
__device__ unsigned d_wb0[8 * 128];
__device__ unsigned d_wb1[4 * 128];
__device__ unsigned d_wb2[4 * 40];
__device__ float    d_al0[128];
__device__ float    d_al1[128];
__device__ float    d_al2[40];

// ---------------- edge dtype detection (int32 vs int64) ----------------
__global__ void k_detect(const void* e) {
    __shared__ int s;
    if (threadIdx.x == 0) s = 0;
    __syncthreads();
    const unsigned* w = (const unsigned*)e;
    int z = 0;
    for (int i = threadIdx.x; i < 1024; i += blockDim.x)
        if (w[2 * i + 1] == 0) z++;   // int64 positive values => high words all zero
    atomicAdd(&s, z);
    __syncthreads();
    if (threadIdx.x == 0) d_is64 = (s > 512);
}

__device__ __forceinline__ int ld_edge(const void* e, long long idx, int is64) {
    return is64 ? (int)((const long long*)e)[idx] : ((const int*)e)[idx];
}

__global__ void k_zero(int n) {
    int i = blockIdx.x * blockDim.x + threadIdx.x;
    if (i < n) { d_cnt[i] = 0; d_cur[i] = 0; }
}

// ---------------- deterministic column mean of x (N x 256) ----------------
__global__ void k_colsum_part(const float* __restrict__ x, int n) {
    int rows = (n + 511) / 512;
    int r0 = blockIdx.x * rows, r1 = min(n, r0 + rows);
    float s = 0.f;
    for (int r = r0; r < r1; r++) s += x[(long long)r * 256 + threadIdx.x];
    d_part[blockIdx.x * 256 + threadIdx.x] = s;
}

// one block per column; 256 threads reduce 512 partials
__global__ void k_colsum_fin(int n) {
    __shared__ float red[256];
    int c = blockIdx.x, t = threadIdx.x;
    float s = d_part[t * 256 + c] + d_part[(t + 256) * 256 + c];
    red[t] = s;
    __syncthreads();
    for (int off = 128; off >= 32; off >>= 1) {
        if (t < off) red[t] += red[t + off];
        __syncthreads();
    }
    if (t < 32) {
        float v = red[t];
        for (int o = 16; o; o >>= 1) v += __shfl_xor_sync(FULLM, v, o);
        if (t == 0) d_mu[c] = v / (float)n;
    }
}

// ---------------- degree histogram over dst ----------------
__global__ void k_deg(const void* e, long long E) {
    long long i = (long long)blockIdx.x * blockDim.x + threadIdx.x;
    if (i < E) {
        int is64 = d_is64;
        int dd = ld_edge(e, E + i, is64);
        atomicAdd(&d_cnt[dd], 1);
    }
}

// ---------------- exclusive scan of counts -> CSR offsets; dinv = rsqrt(deg+1) ----------------
__global__ void k_scan(int n) {
    __shared__ int ss[1024];
    int tid = threadIdx.x;
    int chunk = (n + 1023) / 1024;
    int c0 = tid * chunk, c1 = min(n, c0 + chunk);
    int s = 0;
    for (int i = c0; i < c1; i++) s += d_cnt[i];
    ss[tid] = s;
    __syncthreads();
    for (int off = 1; off < 1024; off <<= 1) {
        int v = (tid >= off) ? ss[tid - off] : 0;
        __syncthreads();
        ss[tid] += v;
        __syncthreads();
    }
    int run = ss[tid] - s;   // exclusive prefix of this thread's chunk
    for (int i = c0; i < c1; i++) {
        d_off[i] = run;
        run += d_cnt[i];
        d_dinv[i] = rsqrtf((float)(d_cnt[i] + 1));   // +1: self loop
    }
    if (c0 < n && c1 == n) d_off[n] = run;
}

// ---------------- CSR fill (col = src per dst) ----------------
__global__ void k_csr(const void* e, long long E) {
    long long i = (long long)blockIdx.x * blockDim.x + threadIdx.x;
    if (i < E) {
        int is64 = d_is64;
        int sv = ld_edge(e, i, is64);
        int dv = ld_edge(e, E + i, is64);
        int pos = d_off[dv] + atomicAdd(&d_cur[dv], 1);
        d_col[pos] = sv;
    }
}

// ---------------- weight binarization: bits + alpha (one warp per out column) ----------------
__global__ void k_wprep(const float* __restrict__ W, int K, int OUT, int which) {
    unsigned* wbT = (which == 0) ? d_wb0 : (which == 1) ? d_wb1 : d_wb2;
    float* alpha = (which == 0) ? d_al0 : (which == 1) ? d_al1 : d_al2;
    int j = blockIdx.x, lane = threadIdx.x;
    float s = 0.f;
    int KW = K / 32;
    for (int w = 0; w < KW; w++) {
        float v = W[(long long)(w * 32 + lane) * OUT + j];
        s += fabsf(v);
        unsigned m = __ballot_sync(FULLM, v > 0.f);
        if (lane == 0) wbT[w * OUT + j] = m;
    }
    for (int o = 16; o; o >>= 1) s += __shfl_xor_sync(FULLM, s, o);
    if (lane == 0) alpha[j] = s / (float)K;
}

// ---------------- BN+sign fused: bits0 = (x > mu) packed, one warp per node ----------------
__global__ void k_bnpack(const float* __restrict__ x, int n) {
    __shared__ float smu[256];
    smu[threadIdx.x] = d_mu[threadIdx.x];
    __syncthreads();
    int warp = (blockIdx.x * blockDim.x + threadIdx.x) >> 5;
    int lane = threadIdx.x & 31;
    if (warp >= n) return;
    const float* xr = x + (long long)warp * 256;
#pragma unroll
    for (int w = 0; w < 8; w++) {
        float v = xr[w * 32 + lane];
        unsigned m = __ballot_sync(FULLM, v > smu[w * 32 + lane]);
        if (lane == w) d_bits0[warp * 8 + w] = m;
    }
}

// ---------------- binary matmul via XOR+popcount -> exact cnt stored as half2 ----------------
// g[n, j] = K - 2*popc(a ^ w)   (integer, exact in fp16)
// OUTH = OUT/2 (pairs). ROWH = half2 row stride.
template <int KW, int OUT, int OUTH, int ROWH, int NL, int ITER, int LAYER>
__global__ void k_bmm(int n) {
    const unsigned* bits = (LAYER == 0) ? d_bits0 : (LAYER == 1) ? d_bits1 : d_bits2;
    const unsigned* wbT  = (LAYER == 0) ? d_wb0  : (LAYER == 1) ? d_wb1  : d_wb2;
    int t = threadIdx.x;
    if (t >= NL * OUTH) return;
    int jp = t % OUTH, nl = t / OUTH;
    int j0 = jp * 2;
    unsigned w0[KW], w1[KW];
#pragma unroll
    for (int w = 0; w < KW; w++) {
        w0[w] = wbT[w * OUT + j0];
        w1[w] = wbT[w * OUT + j0 + 1];
    }
    int base = blockIdx.x * (NL * ITER) + nl;
#pragma unroll 4
    for (int it = 0; it < ITER; it++) {
        int nn = base + it * NL;
        if (nn >= n) break;
        const unsigned* ab = bits + (long long)nn * KW;
        int p0 = 0, p1 = 0;
#pragma unroll
        for (int w = 0; w < KW; w++) {
            unsigned a = ab[w];
            p0 += __popc(a ^ w0[w]);
            p1 += __popc(a ^ w1[w]);
        }
        d_g[(long long)nn * ROWH + jp] =
            __floats2half2_rn((float)(KW * 32 - 2 * p0), (float)(KW * 32 - 2 * p1));
    }
}

// ---------------- aggregation (pull, 128 features) fused with bias+sign+bitpack ----------------
// acc_j = dinv[d]*cnt[d][j] + sum_s dinv[s]*cnt[s][j];  v = acc*alpha[j]*dinv[d] + b[j]
template <int OLAYER>
__global__ void k_agg_pack(const float* __restrict__ bias, int n) {
    unsigned* obits = (OLAYER == 1) ? d_bits1 : d_bits2;
    const float* alp = (OLAYER == 1) ? d_al0 : d_al1;
    int wid = (blockIdx.x * blockDim.x + threadIdx.x) >> 5;
    int lane = threadIdx.x & 31;
    if (wid >= n) return;
    const uint2* gp = (const uint2*)d_g;   // 32 uint2 per node row (64 half2)
    float di = d_dinv[wid];
    float4 a0, a1 = make_float4(0.f, 0.f, 0.f, 0.f);
    {   // self loop
        uint2 u = gp[(long long)wid * 32 + lane];
        float2 f0 = __half22float2(*reinterpret_cast<__half2*>(&u.x));
        float2 f1 = __half22float2(*reinterpret_cast<__half2*>(&u.y));
        a0.x = di * f0.x; a0.y = di * f0.y; a0.z = di * f1.x; a0.w = di * f1.y;
    }
    int k = d_off[wid], k1 = d_off[wid + 1];
    for (; k + 2 <= k1; k += 2) {
        int s0 = d_col[k], s1 = d_col[k + 1];
        float ds0 = d_dinv[s0], ds1 = d_dinv[s1];
        uint2 u0 = gp[(long long)s0 * 32 + lane];
        uint2 u1 = gp[(long long)s1 * 32 + lane];
        float2 f;
        f = __half22float2(*reinterpret_cast<__half2*>(&u0.x)); a0.x += ds0 * f.x; a0.y += ds0 * f.y;
        f = __half22float2(*reinterpret_cast<__half2*>(&u0.y)); a0.z += ds0 * f.x; a0.w += ds0 * f.y;
        f = __half22float2(*reinterpret_cast<__half2*>(&u1.x)); a1.x += ds1 * f.x; a1.y += ds1 * f.y;
        f = __half22float2(*reinterpret_cast<__half2*>(&u1.y)); a1.z += ds1 * f.x; a1.w += ds1 * f.y;
    }
    if (k < k1) {
        int s0 = d_col[k];
        float ds0 = d_dinv[s0];
        uint2 u0 = gp[(long long)s0 * 32 + lane];
        float2 f;
        f = __half22float2(*reinterpret_cast<__half2*>(&u0.x)); a0.x += ds0 * f.x; a0.y += ds0 * f.y;
        f = __half22float2(*reinterpret_cast<__half2*>(&u0.y)); a0.z += ds0 * f.x; a0.w += ds0 * f.y;
    }
    float4 al = ((const float4*)alp)[lane];
    float4 b  = ((const float4*)bias)[lane];
    float v0 = (a0.x + a1.x) * al.x * di + b.x;
    float v1 = (a0.y + a1.y) * al.y * di + b.y;
    float v2 = (a0.z + a1.z) * al.z * di + b.z;
    float v3 = (a0.w + a1.w) * al.w * di + b.w;
    unsigned nib = (unsigned)(v0 > 0.f) | ((unsigned)(v1 > 0.f) << 1) |
                   ((unsigned)(v2 > 0.f) << 2) | ((unsigned)(v3 > 0.f) << 3);
    unsigned sh = nib << ((lane & 7) * 4);
    sh |= __shfl_xor_sync(FULLM, sh, 1);
    sh |= __shfl_xor_sync(FULLM, sh, 2);
    sh |= __shfl_xor_sync(FULLM, sh, 4);
    if ((lane & 7) == 0) obits[wid * 4 + (lane >> 3)] = sh;
}

// ---------------- final aggregation (40 features) fused with bias + log_softmax ----------------
__global__ void k_agg_out(const float* __restrict__ bias, float* __restrict__ out, int n) {
    int wid = (blockIdx.x * blockDim.x + threadIdx.x) >> 5;
    int lane = threadIdx.x & 31;
    if (wid >= n) return;
    bool act = lane < 20;
    float di = d_dinv[wid];
    float2 a0 = make_float2(0.f, 0.f), a1 = make_float2(0.f, 0.f);
    if (act) {
        float2 f = __half22float2(d_g[(long long)wid * 20 + lane]);
        a0.x = di * f.x; a0.y = di * f.y;
    }
    int k = d_off[wid], k1 = d_off[wid + 1];
    for (; k + 2 <= k1; k += 2) {
        int s0 = d_col[k], s1 = d_col[k + 1];
        if (act) {
            float ds0 = d_dinv[s0], ds1 = d_dinv[s1];
            float2 f0 = __half22float2(d_g[(long long)s0 * 20 + lane]);
            float2 f1 = __half22float2(d_g[(long long)s1 * 20 + lane]);
            a0.x += ds0 * f0.x; a0.y += ds0 * f0.y;
            a1.x += ds1 * f1.x; a1.y += ds1 * f1.y;
        }
    }
    if (k < k1) {
        int s0 = d_col[k];
        if (act) {
            float ds0 = d_dinv[s0];
            float2 f0 = __half22float2(d_g[(long long)s0 * 20 + lane]);
            a0.x += ds0 * f0.x; a0.y += ds0 * f0.y;
        }
    }
    float v0 = -1e30f, v1 = -1e30f;
    if (act) {
        float2 al = ((const float2*)d_al2)[lane];
        float2 b  = ((const float2*)bias)[lane];
        v0 = (a0.x + a1.x) * al.x * di + b.x;
        v1 = (a0.y + a1.y) * al.y * di + b.y;
    }
    float m = fmaxf(v0, v1);
    for (int o = 16; o; o >>= 1) m = fmaxf(m, __shfl_xor_sync(FULLM, m, o));
    float se = act ? (expf(v0 - m) + expf(v1 - m)) : 0.f;
    for (int o = 16; o; o >>= 1) se += __shfl_xor_sync(FULLM, se, o);
    float lse = logf(se);
    if (act) {
        float2 r;
        r.x = v0 - m - lse;
        r.y = v1 - m - lse;
        ((float2*)out)[(long long)wid * 20 + lane] = r;
    }
}

// ---------------- launch ----------------
extern "C" void kernel_launch(void* const* d_in, const int* in_sizes, int n_in,
                              void* d_out, int out_size) {
    const float* x  = (const float*)d_in[0];
    const void*  ei = d_in[1];
    const float* W0 = (const float*)d_in[2];
    const float* b0 = (const float*)d_in[3];
    const float* W1 = (const float*)d_in[4];
    const float* b1 = (const float*)d_in[5];
    const float* W2 = (const float*)d_in[6];
    const float* b2 = (const float*)d_in[7];
    float* out = (float*)d_out;

    int N = in_sizes[0] / 256;
    long long E = (long long)in_sizes[1] / 2;

    int nb256 = (N + 255) / 256;
    int eb = (int)((E + 255) / 256);
    int wb = (N + 7) / 8;       // warp-per-node kernels, 256-thread blocks

    k_detect<<<1, 256>>>(ei);
    k_zero<<<nb256, 256>>>(N);
    k_colsum_part<<<512, 256>>>(x, N);
    k_colsum_fin<<<256, 256>>>(N);
    k_deg<<<eb, 256>>>(ei, E);
    k_scan<<<1, 1024>>>(N);
    k_csr<<<eb, 256>>>(ei, E);
    k_wprep<<<128, 32>>>(W0, 256, 128, 0);
    k_wprep<<<128, 32>>>(W1, 128, 128, 1);
    k_wprep<<<40, 32>>>(W2, 128, 40, 2);
    k_bnpack<<<wb, 256>>>(x, N);

    // layer 0: K=256 -> H=128  (64 pairs; 128 thr = 2 nodes/iter, 32 iters -> 64 nodes/block)
    k_bmm<8, 128, 64, 64, 2, 32, 0><<<(N + 63) / 64, 128>>>(N);
    k_agg_pack<1><<<wb, 256>>>(b0, N);
    // layer 1: K=128 -> H=128
    k_bmm<4, 128, 64, 64, 2, 32, 1><<<(N + 63) / 64, 128>>>(N);
    k_agg_pack<2><<<wb, 256>>>(b1, N);
    // layer 2: K=128 -> OUT=40 (20 pairs; 120 thr = 6 nodes/iter, 32 iters -> 192/block)
    k_bmm<4, 40, 20, 20, 6, 32, 2><<<(N + 191) / 192, 128>>>(N);
    k_agg_out<<<wb, 256>>>(b2, out, N);
}

// round 4
// speedup vs baseline: 1.0860x; 1.0860x over previous
#include <cuda_runtime.h>
#include <cuda_fp16.h>
#include <math.h>

#define FULLM 0xffffffffu
static const int NMAX = 100352;
static const int EMAX = 1700000;

// ---------------- device scratch ----------------
__device__ int      d_cnt[NMAX];
__device__ int      d_cur[NMAX];
__device__ int      d_off[NMAX + 1];
__device__ float    d_dinv[NMAX];
__device__ int      d_col[EMAX];
__device__ unsigned d_bits0[NMAX * 8];
__device__ unsigned d_bits1[NMAX * 4];
__device__ unsigned d_bits2[NMAX * 4];
__device__ __align__(16) __half2 d_g[NMAX * 64];   // raw cnt (exact integers in fp16)
__device__ float    d_mu[256];
__device__ float    d_part[512 * 256];
__device__ unsigned d_wb0[8 * 128];
__device__ unsigned d_wb1[4 * 128];
__device__ unsigned d_wb2[4 * 40];
__device__ float    d_al0[128];
__device__ float    d_al1[128];
__device__ float    d_al2[40];

// inline edge-dtype detection (int32 vs int64), per warp
__device__ __forceinline__ int detect64(const void* e) {
    const unsigned* w = (const unsigned*)e;
    int lane = threadIdx.x & 31;
    unsigned h0 = w[2 * lane + 1];
    unsigned h1 = w[64 + 2 * lane + 1];
    int z = __popc(__ballot_sync(FULLM, h0 == 0)) + __popc(__ballot_sync(FULLM, h1 == 0));
    return z >= 32;
}
__device__ __forceinline__ int ld_edge(const void* e, long long idx, int is64) {
    return is64 ? (int)((const long long*)e)[idx] : ((const int*)e)[idx];
}

// ============ K1: colsum_part (512 blocks) | wprep (37 blocks) | zero (100 blocks) ============
__global__ void k_prep(const float* __restrict__ x,
                       const float* __restrict__ W0,
                       const float* __restrict__ W1,
                       const float* __restrict__ W2, int n) {
    int bid = blockIdx.x;
    if (bid < 512) {                       // column partial sums of x
        int rows = (n + 511) / 512;
        int r0 = bid * rows, r1 = min(n, r0 + rows);
        float s = 0.f;
        for (int r = r0; r < r1; r++) s += x[(long long)r * 256 + threadIdx.x];
        d_part[bid * 256 + threadIdx.x] = s;
    } else if (bid < 549) {                // weight binarization: 296 warps
        int W = (bid - 512) * 8 + (threadIdx.x >> 5);
        int lane = threadIdx.x & 31;
        const float* Wsrc; unsigned* wbT; float* alpha; int K, OUT, j;
        if (W < 128)      { Wsrc = W0; wbT = d_wb0; alpha = d_al0; K = 256; OUT = 128; j = W; }
        else if (W < 256) { Wsrc = W1; wbT = d_wb1; alpha = d_al1; K = 128; OUT = 128; j = W - 128; }
        else if (W < 296) { Wsrc = W2; wbT = d_wb2; alpha = d_al2; K = 128; OUT = 40;  j = W - 256; }
        else return;
        float s = 0.f;
        int KW = K / 32;
        for (int w = 0; w < KW; w++) {
            float v = Wsrc[(long long)(w * 32 + lane) * OUT + j];
            s += fabsf(v);
            unsigned m = __ballot_sync(FULLM, v > 0.f);
            if (lane == 0) wbT[w * OUT + j] = m;
        }
        for (int o = 16; o; o >>= 1) s += __shfl_xor_sync(FULLM, s, o);
        if (lane == 0) alpha[j] = s / (float)K;
    } else {                               // zero cnt/cur
        int idx = (bid - 549) * 256 + threadIdx.x;
        for (int i = idx; i < NMAX; i += 100 * 256) { d_cnt[i] = 0; d_cur[i] = 0; }
    }
}

// ============ K2: colsum_fin (256 blocks) | degree histogram (rest) ============
__global__ void k_fin_deg(const void* __restrict__ e, long long E, int n) {
    int bid = blockIdx.x;
    if (bid < 256) {
        __shared__ float red[256];
        int c = bid, t = threadIdx.x;
        red[t] = d_part[t * 256 + c] + d_part[(t + 256) * 256 + c];
        __syncthreads();
        for (int off = 128; off >= 32; off >>= 1) {
            if (t < off) red[t] += red[t + off];
            __syncthreads();
        }
        if (t < 32) {
            float v = red[t];
            for (int o = 16; o; o >>= 1) v += __shfl_xor_sync(FULLM, v, o);
            if (t == 0) d_mu[c] = v / (float)n;
        }
    } else {
        int is64 = detect64(e);
        long long i = (long long)(bid - 256) * blockDim.x + threadIdx.x;
        if (i < E) atomicAdd(&d_cnt[ld_edge(e, E + i, is64)], 1);
    }
}

// ============ K3: bnpack (wb blocks) | block-scan (last block) ============
__global__ void k_bnpack_scan(const float* __restrict__ x, int n, int wb) {
    int bid = blockIdx.x;
    if (bid < wb) {
        __shared__ float smu[256];
        smu[threadIdx.x] = d_mu[threadIdx.x];
        __syncthreads();
        int warp = (bid * 256 + threadIdx.x) >> 5;
        int lane = threadIdx.x & 31;
        if (warp >= n) return;
        const float* xr = x + (long long)warp * 256;
#pragma unroll
        for (int w = 0; w < 8; w++) {
            float v = xr[w * 32 + lane];
            unsigned m = __ballot_sync(FULLM, v > smu[w * 32 + lane]);
            if (lane == w) d_bits0[warp * 8 + w] = m;
        }
    } else {
        __shared__ int wsum[8];
        int t = threadIdx.x, lane = t & 31, wrp = t >> 5;
        int chunk = ((n + 255) / 256 + 3) & ~3;
        int c0 = t * chunk, c1 = min(n, c0 + chunk);
        int s = 0, i = c0;
        for (; i + 4 <= c1; i += 4) {
            int4 v = *(const int4*)(d_cnt + i);
            s += v.x + v.y + v.z + v.w;
        }
        for (; i < c1; i++) s += d_cnt[i];
        int incl = s;
        for (int o = 1; o < 32; o <<= 1) {
            int v = __shfl_up_sync(FULLM, incl, o);
            if (lane >= o) incl += v;
        }
        if (lane == 31) wsum[wrp] = incl;
        __syncthreads();
        if (wrp == 0) {
            int v = (lane < 8) ? wsum[lane] : 0;
            for (int o = 1; o < 8; o <<= 1) {
                int u = __shfl_up_sync(FULLM, v, o);
                if (lane >= o) v += u;
            }
            if (lane < 8) wsum[lane] = v;
        }
        __syncthreads();
        int run = incl - s + (wrp ? wsum[wrp - 1] : 0);
        for (i = c0; i < c1; i++) {
            int c = d_cnt[i];
            d_off[i] = run;
            run += c;
            d_dinv[i] = rsqrtf((float)(c + 1));
        }
        if (c0 < n && c1 == n) d_off[n] = run;
    }
}

// ============ CSR fill ============
__global__ void k_csr(const void* __restrict__ e, long long E) {
    int is64 = detect64(e);
    long long i = (long long)blockIdx.x * blockDim.x + threadIdx.x;
    if (i < E) {
        int sv = ld_edge(e, i, is64);
        int dv = ld_edge(e, E + i, is64);
        int pos = d_off[dv] + atomicAdd(&d_cur[dv], 1);
        d_col[pos] = sv;
    }
}

// ============ binary matmul (smem-staged bits) -> exact cnt as half2 ============
template <int KW, int OUT, int OUTH, int NPB, int NL, int ITER, int LAYER>
__global__ void k_bmm(int n) {
    __shared__ unsigned sbits[NPB * KW];
    const unsigned* bits = (LAYER == 0) ? d_bits0 : (LAYER == 1) ? d_bits1 : d_bits2;
    const unsigned* wbT  = (LAYER == 0) ? d_wb0  : (LAYER == 1) ? d_wb1  : d_wb2;
    int base = blockIdx.x * NPB;
    const int4* src = (const int4*)(bits + (long long)base * KW);
    for (int i = threadIdx.x; i < NPB * KW / 4; i += blockDim.x)
        ((int4*)sbits)[i] = src[i];
    __syncthreads();
    int t = threadIdx.x;
    if (t >= NL * OUTH) return;
    int jp = t % OUTH, nl = t / OUTH, j0 = jp * 2;
    unsigned w0[KW], w1[KW];
#pragma unroll
    for (int w = 0; w < KW; w++) { w0[w] = wbT[w * OUT + j0]; w1[w] = wbT[w * OUT + j0 + 1]; }
#pragma unroll 4
    for (int it = 0; it < ITER; it++) {
        int loc = it * NL + nl;
        int nn = base + loc;
        if (nn >= n) break;
        const unsigned* ab = sbits + loc * KW;
        int p0 = 0, p1 = 0;
#pragma unroll
        for (int w = 0; w < KW; w++) {
            unsigned a = ab[w];
            p0 += __popc(a ^ w0[w]);
            p1 += __popc(a ^ w1[w]);
        }
        d_g[(long long)nn * OUTH + jp] =
            __floats2half2_rn((float)(KW * 32 - 2 * p0), (float)(KW * 32 - 2 * p1));
    }
}

__device__ __forceinline__ void acc4s(float4& a, uint2 u, float s) {
    float2 f0 = __half22float2(*reinterpret_cast<__half2*>(&u.x));
    float2 f1 = __half22float2(*reinterpret_cast<__half2*>(&u.y));
    a.x += s * f0.x; a.y += s * f0.y; a.z += s * f1.x; a.w += s * f1.y;
}

// ============ aggregation (128 feats) + bias + sign + bitpack ============
template <int OLAYER>
__global__ void k_agg_pack(const float* __restrict__ bias, int n) {
    unsigned* obits = (OLAYER == 1) ? d_bits1 : d_bits2;
    const float* alp = (OLAYER == 1) ? d_al0 : d_al1;
    int wid = (blockIdx.x * blockDim.x + threadIdx.x) >> 5;
    int lane = threadIdx.x & 31;
    if (wid >= n) return;
    const uint2* gp = (const uint2*)d_g;
    float di = d_dinv[wid];
    float4 A = make_float4(0.f, 0.f, 0.f, 0.f), B = A;
    acc4s(A, gp[(long long)wid * 32 + lane], di);      // self loop
    int k = d_off[wid], k1 = d_off[wid + 1];
    for (; k + 4 <= k1; k += 4) {
        int c0 = d_col[k], c1 = d_col[k + 1], c2 = d_col[k + 2], c3 = d_col[k + 3];
        float s0 = d_dinv[c0], s1 = d_dinv[c1], s2 = d_dinv[c2], s3 = d_dinv[c3];
        uint2 u0 = gp[(long long)c0 * 32 + lane];
        uint2 u1 = gp[(long long)c1 * 32 + lane];
        uint2 u2 = gp[(long long)c2 * 32 + lane];
        uint2 u3 = gp[(long long)c3 * 32 + lane];
        acc4s(A, u0, s0); acc4s(B, u1, s1); acc4s(A, u2, s2); acc4s(B, u3, s3);
    }
    for (; k < k1; k++) {
        int c = d_col[k];
        acc4s(B, gp[(long long)c * 32 + lane], d_dinv[c]);
    }
    float4 al = ((const float4*)alp)[lane];
    float4 b  = ((const float4*)bias)[lane];
    float v0 = (A.x + B.x) * al.x * di + b.x;
    float v1 = (A.y + B.y) * al.y * di + b.y;
    float v2 = (A.z + B.z) * al.z * di + b.z;
    float v3 = (A.w + B.w) * al.w * di + b.w;
    unsigned nib = (unsigned)(v0 > 0.f) | ((unsigned)(v1 > 0.f) << 1) |
                   ((unsigned)(v2 > 0.f) << 2) | ((unsigned)(v3 > 0.f) << 3);
    unsigned sh = nib << ((lane & 7) * 4);
    sh |= __shfl_xor_sync(FULLM, sh, 1);
    sh |= __shfl_xor_sync(FULLM, sh, 2);
    sh |= __shfl_xor_sync(FULLM, sh, 4);
    if ((lane & 7) == 0) obits[wid * 4 + (lane >> 3)] = sh;
}

// ============ final aggregation (40 feats) + bias + log_softmax ============
__global__ void k_agg_out(const float* __restrict__ bias, float* __restrict__ out, int n) {
    int wid = (blockIdx.x * blockDim.x + threadIdx.x) >> 5;
    int lane = threadIdx.x & 31;
    if (wid >= n) return;
    bool act = lane < 20;
    float di = d_dinv[wid];
    float2 A = make_float2(0.f, 0.f), B = A;
    if (act) {
        float2 f = __half22float2(d_g[(long long)wid * 20 + lane]);
        A.x += di * f.x; A.y += di * f.y;
    }
    int k = d_off[wid], k1 = d_off[wid + 1];
    for (; k + 4 <= k1; k += 4) {
        int c0 = d_col[k], c1 = d_col[k + 1], c2 = d_col[k + 2], c3 = d_col[k + 3];
        float s0 = d_dinv[c0], s1 = d_dinv[c1], s2 = d_dinv[c2], s3 = d_dinv[c3];
        if (act) {
            float2 f0 = __half22float2(d_g[(long long)c0 * 20 + lane]);
            float2 f1 = __half22float2(d_g[(long long)c1 * 20 + lane]);
            float2 f2 = __half22float2(d_g[(long long)c2 * 20 + lane]);
            float2 f3 = __half22float2(d_g[(long long)c3 * 20 + lane]);
            A.x += s0 * f0.x; A.y += s0 * f0.y; B.x += s1 * f1.x; B.y += s1 * f1.y;
            A.x += s2 * f2.x; A.y += s2 * f2.y; B.x += s3 * f3.x; B.y += s3 * f3.y;
        }
    }
    for (; k < k1; k++) {
        int c = d_col[k];
        float s = d_dinv[c];
        if (act) {
            float2 f = __half22float2(d_g[(long long)c * 20 + lane]);
            B.x += s * f.x; B.y += s * f.y;
        }
    }
    float v0 = -1e30f, v1 = -1e30f;
    if (act) {
        float2 al = ((const float2*)d_al2)[lane];
        float2 b  = ((const float2*)bias)[lane];
        v0 = (A.x + B.x) * al.x * di + b.x;
        v1 = (A.y + B.y) * al.y * di + b.y;
    }
    float m = fmaxf(v0, v1);
    for (int o = 16; o; o >>= 1) m = fmaxf(m, __shfl_xor_sync(FULLM, m, o));
    float se = act ? (expf(v0 - m) + expf(v1 - m)) : 0.f;
    for (int o = 16; o; o >>= 1) se += __shfl_xor_sync(FULLM, se, o);
    float lse = logf(se);
    if (act) {
        float2 r;
        r.x = v0 - m - lse;
        r.y = v1 - m - lse;
        ((float2*)out)[(long long)wid * 20 + lane] = r;
    }
}

// ---------------- launch ----------------
extern "C" void kernel_launch(void* const* d_in, const int* in_sizes, int n_in,
                              void* d_out, int out_size) {
    const float* x  = (const float*)d_in[0];
    const void*  ei = d_in[1];
    const float* W0 = (const float*)d_in[2];
    const float* b0 = (const float*)d_in[3];
    const float* W1 = (const float*)d_in[4];
    const float* b1 = (const float*)d_in[5];
    const float* W2 = (const float*)d_in[6];
    const float* b2 = (const float*)d_in[7];
    float* out = (float*)d_out;

    int N = in_sizes[0] / 256;
    long long E = (long long)in_sizes[1] / 2;

    int eb = (int)((E + 255) / 256);
    int wb = (N + 7) / 8;

    k_prep<<<649, 256>>>(x, W0, W1, W2, N);             // 1
    k_fin_deg<<<256 + eb, 256>>>(ei, E, N);             // 2
    k_bnpack_scan<<<wb + 1, 256>>>(x, N, wb);           // 3
    k_bmm<8, 128, 64, 64, 2, 32, 0><<<(N + 63) / 64, 128>>>(N);  // 4 (PROFILED)
    k_csr<<<eb, 256>>>(ei, E);                          // 5
    k_agg_pack<1><<<wb, 256>>>(b0, N);                  // 6
    k_bmm<4, 128, 64, 64, 2, 32, 1><<<(N + 63) / 64, 128>>>(N);  // 7
    k_agg_pack<2><<<wb, 256>>>(b1, N);                  // 8
    k_bmm<4, 40, 20, 192, 6, 32, 2><<<(N + 191) / 192, 128>>>(N); // 9
    k_agg_out<<<wb, 256>>>(b2, out, N);                 // 10
}

// round 5
// speedup vs baseline: 1.1077x; 1.0200x over previous
#include <cuda_runtime.h>
#include <cuda_fp16.h>
#include <math.h>

#define FULLM 0xffffffffu
static const int NMAX = 100352;
static const int EMAX = 1700000;

// ---------------- device scratch ----------------
__device__ int      d_cnt[NMAX];
__device__ int      d_cur[NMAX];
__device__ int      d_off[NMAX + 1];
__device__ float    d_dinv[NMAX];
__device__ int      d_col[EMAX];
__device__ unsigned d_bits0[NMAX * 8];
__device__ unsigned d_bits1[NMAX * 4];
__device__ unsigned d_bits2[NMAX * 4];
__device__ __align__(16) __half2 d_g[NMAX * 64];   // raw cnt (exact integers in fp16)
__device__ float    d_mu[256];
__device__ float    d_part[512 * 256];
__device__ unsigned d_wb0[8 * 128];
__device__ unsigned d_wb1[4 * 128];
__device__ unsigned d_wb2[4 * 40];
__device__ float    d_al0[128];
__device__ float    d_al1[128];
__device__ float    d_al2[40];

__device__ __forceinline__ int detect64(const void* e) {
    const unsigned* w = (const unsigned*)e;
    int lane = threadIdx.x & 31;
    unsigned h0 = w[2 * lane + 1];
    unsigned h1 = w[64 + 2 * lane + 1];
    int z = __popc(__ballot_sync(FULLM, h0 == 0)) + __popc(__ballot_sync(FULLM, h1 == 0));
    return z >= 32;
}
__device__ __forceinline__ int ld_edge(const void* e, long long idx, int is64) {
    return is64 ? (int)((const long long*)e)[idx] : ((const int*)e)[idx];
}

// ============ K1: colsum_part | wprep | zero ============
__global__ void k_prep(const float* __restrict__ x,
                       const float* __restrict__ W0,
                       const float* __restrict__ W1,
                       const float* __restrict__ W2, int n) {
    int bid = blockIdx.x;
    if (bid < 512) {
        int rows = (n + 511) / 512;
        int r0 = bid * rows, r1 = min(n, r0 + rows);
        float s = 0.f;
        for (int r = r0; r < r1; r++) s += x[(long long)r * 256 + threadIdx.x];
        d_part[bid * 256 + threadIdx.x] = s;
    } else if (bid < 549) {
        int W = (bid - 512) * 8 + (threadIdx.x >> 5);
        int lane = threadIdx.x & 31;
        const float* Wsrc; unsigned* wbT; float* alpha; int K, OUT, j;
        if (W < 128)      { Wsrc = W0; wbT = d_wb0; alpha = d_al0; K = 256; OUT = 128; j = W; }
        else if (W < 256) { Wsrc = W1; wbT = d_wb1; alpha = d_al1; K = 128; OUT = 128; j = W - 128; }
        else if (W < 296) { Wsrc = W2; wbT = d_wb2; alpha = d_al2; K = 128; OUT = 40;  j = W - 256; }
        else return;
        float s = 0.f;
        int KW = K / 32;
        for (int w = 0; w < KW; w++) {
            float v = Wsrc[(long long)(w * 32 + lane) * OUT + j];
            s += fabsf(v);
            unsigned m = __ballot_sync(FULLM, v > 0.f);
            if (lane == 0) wbT[w * OUT + j] = m;
        }
        for (int o = 16; o; o >>= 1) s += __shfl_xor_sync(FULLM, s, o);
        if (lane == 0) alpha[j] = s / (float)K;
    } else {
        int idx = (bid - 549) * 256 + threadIdx.x;
        for (int i = idx; i < NMAX; i += 100 * 256) { d_cnt[i] = 0; d_cur[i] = 0; }
    }
}

// ============ K2: colsum_fin | degree histogram ============
__global__ void k_fin_deg(const void* __restrict__ e, long long E, int n) {
    int bid = blockIdx.x;
    if (bid < 256) {
        __shared__ float red[256];
        int c = bid, t = threadIdx.x;
        red[t] = d_part[t * 256 + c] + d_part[(t + 256) * 256 + c];
        __syncthreads();
        for (int off = 128; off >= 32; off >>= 1) {
            if (t < off) red[t] += red[t + off];
            __syncthreads();
        }
        if (t < 32) {
            float v = red[t];
            for (int o = 16; o; o >>= 1) v += __shfl_xor_sync(FULLM, v, o);
            if (t == 0) d_mu[c] = v / (float)n;
        }
    } else {
        int is64 = detect64(e);
        long long i = (long long)(bid - 256) * blockDim.x + threadIdx.x;
        if (i < E) atomicAdd(&d_cnt[ld_edge(e, E + i, is64)], 1);
    }
}

// ============ K3: bnpack | block-scan ============
__global__ void k_bnpack_scan(const float* __restrict__ x, int n, int wb) {
    int bid = blockIdx.x;
    if (bid < wb) {
        __shared__ float smu[256];
        smu[threadIdx.x] = d_mu[threadIdx.x];
        __syncthreads();
        int warp = (bid * 256 + threadIdx.x) >> 5;
        int lane = threadIdx.x & 31;
        if (warp >= n) return;
        const float* xr = x + (long long)warp * 256;
#pragma unroll
        for (int w = 0; w < 8; w++) {
            float v = xr[w * 32 + lane];
            unsigned m = __ballot_sync(FULLM, v > smu[w * 32 + lane]);
            if (lane == w) d_bits0[warp * 8 + w] = m;
        }
    } else {
        __shared__ int wsum[8];
        int t = threadIdx.x, lane = t & 31, wrp = t >> 5;
        int chunk = ((n + 255) / 256 + 3) & ~3;
        int c0 = t * chunk, c1 = min(n, c0 + chunk);
        int s = 0, i = c0;
        for (; i + 4 <= c1; i += 4) {
            int4 v = *(const int4*)(d_cnt + i);
            s += v.x + v.y + v.z + v.w;
        }
        for (; i < c1; i++) s += d_cnt[i];
        int incl = s;
        for (int o = 1; o < 32; o <<= 1) {
            int v = __shfl_up_sync(FULLM, incl, o);
            if (lane >= o) incl += v;
        }
        if (lane == 31) wsum[wrp] = incl;
        __syncthreads();
        if (wrp == 0) {
            int v = (lane < 8) ? wsum[lane] : 0;
            for (int o = 1; o < 8; o <<= 1) {
                int u = __shfl_up_sync(FULLM, v, o);
                if (lane >= o) v += u;
            }
            if (lane < 8) wsum[lane] = v;
        }
        __syncthreads();
        int run = incl - s + (wrp ? wsum[wrp - 1] : 0);
        for (i = c0; i < c1; i++) {
            int c = d_cnt[i];
            d_off[i] = run;
            run += c;
            d_dinv[i] = rsqrtf((float)(c + 1));
        }
        if (c0 < n && c1 == n) d_off[n] = run;
    }
}

// bmm body: XOR+popcount -> exact cnt as half2 (256-thread or 128-thread variants)
template <int KW, int OUT, int OUTH, int NPB, int NL, int ITER>
__device__ __forceinline__ void bmm_body(const unsigned* __restrict__ bits,
                                         const unsigned* __restrict__ wbT,
                                         unsigned* sbits, int blk, int n) {
    int base = blk * NPB;
    const int4* src = (const int4*)(bits + (long long)base * KW);
    for (int i = threadIdx.x; i < NPB * KW / 4; i += blockDim.x)
        ((int4*)sbits)[i] = src[i];
    __syncthreads();
    int t = threadIdx.x;
    if (t >= NL * OUTH) return;
    int jp = t % OUTH, nl = t / OUTH, j0 = jp * 2;
    unsigned w0[KW], w1[KW];
#pragma unroll
    for (int w = 0; w < KW; w++) { w0[w] = wbT[w * OUT + j0]; w1[w] = wbT[w * OUT + j0 + 1]; }
#pragma unroll 4
    for (int it = 0; it < ITER; it++) {
        int loc = it * NL + nl;
        int nn = base + loc;
        if (nn >= n) break;
        const unsigned* ab = sbits + loc * KW;
        int p0 = 0, p1 = 0;
#pragma unroll
        for (int w = 0; w < KW; w++) {
            unsigned a = ab[w];
            p0 += __popc(a ^ w0[w]);
            p1 += __popc(a ^ w1[w]);
        }
        d_g[(long long)nn * OUTH + jp] =
            __floats2half2_rn((float)(KW * 32 - 2 * p0), (float)(KW * 32 - 2 * p1));
    }
}

// ============ K4: bmm layer 0 (256 thr) | CSR fill — independent, merged ============
__global__ void k_bmm0_csr(const void* __restrict__ e, long long E, int n, int bmmb) {
    __shared__ unsigned sbits[64 * 8];
    if ((int)blockIdx.x < bmmb) {
        bmm_body<8, 128, 64, 64, 4, 16>(d_bits0, d_wb0, sbits, blockIdx.x, n);
    } else {
        int is64 = detect64(e);
        long long i = (long long)(blockIdx.x - bmmb) * blockDim.x + threadIdx.x;
        if (i < E) {
            int sv = ld_edge(e, i, is64);
            int dv = ld_edge(e, E + i, is64);
            int pos = d_off[dv] + atomicAdd(&d_cur[dv], 1);
            d_col[pos] = sv;
        }
    }
}

template <int KW, int OUT, int OUTH, int NPB, int NL, int ITER, int LAYER>
__global__ void k_bmm(int n) {
    __shared__ unsigned sbits[NPB * KW];
    const unsigned* bits = (LAYER == 1) ? d_bits1 : d_bits2;
    const unsigned* wbT  = (LAYER == 1) ? d_wb1  : d_wb2;
    bmm_body<KW, OUT, OUTH, NPB, NL, ITER>(bits, wbT, sbits, blockIdx.x, n);
}

__device__ __forceinline__ void acc4s(float4& a, uint2 u, float s) {
    float2 f0 = __half22float2(*reinterpret_cast<__half2*>(&u.x));
    float2 f1 = __half22float2(*reinterpret_cast<__half2*>(&u.y));
    a.x += s * f0.x; a.y += s * f0.y; a.z += s * f1.x; a.w += s * f1.y;
}

// ============ aggregation (128 feats): two-phase 8-deep unrolled gather ============
template <int OLAYER>
__global__ void k_agg_pack(const float* __restrict__ bias, int n) {
    unsigned* obits = (OLAYER == 1) ? d_bits1 : d_bits2;
    const float* alp = (OLAYER == 1) ? d_al0 : d_al1;
    int wid = (blockIdx.x * blockDim.x + threadIdx.x) >> 5;
    int lane = threadIdx.x & 31;
    if (wid >= n) return;
    const uint2* gp = (const uint2*)d_g;
    float di = d_dinv[wid];
    float4 A = make_float4(0.f, 0.f, 0.f, 0.f), B = A;
    acc4s(A, gp[(long long)wid * 32 + lane], di);      // self loop
    int k = d_off[wid], k1 = d_off[wid + 1];
    for (; k + 8 <= k1; k += 8) {
        int c[8];
#pragma unroll
        for (int j = 0; j < 8; j++) c[j] = d_col[k + j];
        float s[8];
        uint2 u[8];
#pragma unroll
        for (int j = 0; j < 8; j++) s[j] = d_dinv[c[j]];
#pragma unroll
        for (int j = 0; j < 8; j++) u[j] = gp[(long long)c[j] * 32 + lane];
#pragma unroll
        for (int j = 0; j < 8; j++) acc4s((j & 1) ? B : A, u[j], s[j]);
    }
    if (k + 4 <= k1) {
        int c[4];
#pragma unroll
        for (int j = 0; j < 4; j++) c[j] = d_col[k + j];
        float s[4];
        uint2 u[4];
#pragma unroll
        for (int j = 0; j < 4; j++) s[j] = d_dinv[c[j]];
#pragma unroll
        for (int j = 0; j < 4; j++) u[j] = gp[(long long)c[j] * 32 + lane];
#pragma unroll
        for (int j = 0; j < 4; j++) acc4s((j & 1) ? B : A, u[j], s[j]);
        k += 4;
    }
    for (; k < k1; k++) {
        int c = d_col[k];
        acc4s(B, gp[(long long)c * 32 + lane], d_dinv[c]);
    }
    float4 al = ((const float4*)alp)[lane];
    float4 b  = ((const float4*)bias)[lane];
    float v0 = (A.x + B.x) * al.x * di + b.x;
    float v1 = (A.y + B.y) * al.y * di + b.y;
    float v2 = (A.z + B.z) * al.z * di + b.z;
    float v3 = (A.w + B.w) * al.w * di + b.w;
    unsigned nib = (unsigned)(v0 > 0.f) | ((unsigned)(v1 > 0.f) << 1) |
                   ((unsigned)(v2 > 0.f) << 2) | ((unsigned)(v3 > 0.f) << 3);
    unsigned sh = nib << ((lane & 7) * 4);
    sh |= __shfl_xor_sync(FULLM, sh, 1);
    sh |= __shfl_xor_sync(FULLM, sh, 2);
    sh |= __shfl_xor_sync(FULLM, sh, 4);
    if ((lane & 7) == 0) obits[wid * 4 + (lane >> 3)] = sh;
}

// ============ final aggregation (40 feats) + log_softmax, 8-deep unrolled ============
__global__ void k_agg_out(const float* __restrict__ bias, float* __restrict__ out, int n) {
    int wid = (blockIdx.x * blockDim.x + threadIdx.x) >> 5;
    int lane = threadIdx.x & 31;
    if (wid >= n) return;
    bool act = lane < 20;
    float di = d_dinv[wid];
    float2 A = make_float2(0.f, 0.f), B = A;
    if (act) {
        float2 f = __half22float2(d_g[(long long)wid * 20 + lane]);
        A.x += di * f.x; A.y += di * f.y;
    }
    int k = d_off[wid], k1 = d_off[wid + 1];
    for (; k + 8 <= k1; k += 8) {
        int c[8];
#pragma unroll
        for (int j = 0; j < 8; j++) c[j] = d_col[k + j];
        float s[8];
        float2 f[8];
#pragma unroll
        for (int j = 0; j < 8; j++) s[j] = d_dinv[c[j]];
        if (act) {
#pragma unroll
            for (int j = 0; j < 8; j++) f[j] = __half22float2(d_g[(long long)c[j] * 20 + lane]);
#pragma unroll
            for (int j = 0; j < 8; j++) {
                if (j & 1) { B.x += s[j] * f[j].x; B.y += s[j] * f[j].y; }
                else       { A.x += s[j] * f[j].x; A.y += s[j] * f[j].y; }
            }
        }
    }
    for (; k < k1; k++) {
        int c = d_col[k];
        float s = d_dinv[c];
        if (act) {
            float2 f = __half22float2(d_g[(long long)c * 20 + lane]);
            B.x += s * f.x; B.y += s * f.y;
        }
    }
    float v0 = -1e30f, v1 = -1e30f;
    if (act) {
        float2 al = ((const float2*)d_al2)[lane];
        float2 b  = ((const float2*)bias)[lane];
        v0 = (A.x + B.x) * al.x * di + b.x;
        v1 = (A.y + B.y) * al.y * di + b.y;
    }
    float m = fmaxf(v0, v1);
    for (int o = 16; o; o >>= 1) m = fmaxf(m, __shfl_xor_sync(FULLM, m, o));
    float se = act ? (expf(v0 - m) + expf(v1 - m)) : 0.f;
    for (int o = 16; o; o >>= 1) se += __shfl_xor_sync(FULLM, se, o);
    float lse = logf(se);
    if (act) {
        float2 r;
        r.x = v0 - m - lse;
        r.y = v1 - m - lse;
        ((float2*)out)[(long long)wid * 20 + lane] = r;
    }
}

// ---------------- launch ----------------
extern "C" void kernel_launch(void* const* d_in, const int* in_sizes, int n_in,
                              void* d_out, int out_size) {
    const float* x  = (const float*)d_in[0];
    const void*  ei = d_in[1];
    const float* W0 = (const float*)d_in[2];
    const float* b0 = (const float*)d_in[3];
    const float* W1 = (const float*)d_in[4];
    const float* b1 = (const float*)d_in[5];
    const float* W2 = (const float*)d_in[6];
    const float* b2 = (const float*)d_in[7];
    float* out = (float*)d_out;

    int N = in_sizes[0] / 256;
    long long E = (long long)in_sizes[1] / 2;

    int eb = (int)((E + 255) / 256);
    int wb = (N + 7) / 8;
    int bmmb = (N + 63) / 64;

    k_prep<<<649, 256>>>(x, W0, W1, W2, N);                          // 1
    k_fin_deg<<<256 + eb, 256>>>(ei, E, N);                          // 2
    k_bnpack_scan<<<wb + 1, 256>>>(x, N, wb);                        // 3
    k_bmm0_csr<<<bmmb + eb, 256>>>(ei, E, N, bmmb);                  // 4 (PROFILED: bmm0+csr)
    k_agg_pack<1><<<wb, 256>>>(b0, N);                               // 5
    k_bmm<4, 128, 64, 64, 2, 32, 1><<<(N + 63) / 64, 128>>>(N);      // 6
    k_agg_pack<2><<<wb, 256>>>(b1, N);                               // 7
    k_bmm<4, 40, 20, 192, 6, 32, 2><<<(N + 191) / 192, 128>>>(N);    // 8
    k_agg_out<<<wb, 256>>>(b2, out, N);                              // 9
}